// round 10
// baseline (speedup 1.0000x reference)
#include <cuda_runtime.h>
#include <cuda_bf16.h>
#include <stdint.h>

#define BN_EPS 1e-5f

// ---------------------------------------------------------------------------
// Device-global scratch (no allocations allowed)
// ---------------------------------------------------------------------------
__device__ __nv_bfloat16 g_h1[(size_t)64 * 112 * 112 * 32];   // conv1 out, NHWC bf16
__device__ __nv_bfloat16 g_h2[(size_t)64 * 112 * 112 * 64];   // conv2 out, NHWC bf16
__device__ __nv_bfloat16 g_h3[(size_t)64 * 56 * 56 * 128];    // conv3 out, NHWC bf16
__device__ float         g_w1t[27 * 32];                      // conv1 folded fp32 [k][oc]
__device__ __nv_bfloat16 g_wsgn2[64 * 288];                   // conv2 signs [oc][k], k=tap*32+ic
__device__ __nv_bfloat16 g_wsgn3[128 * 576];                  // conv3 signs [oc][k], k=tap*64+ic
__device__ float g_bias1[32];
__device__ float g_scale2[64],  g_bias2[64];
__device__ float g_scale3[128], g_bias3[128];
__device__ float g_wlq[10 * 128];
__device__ float g_pool[64 * 128];
__device__ float g_poolpart[64 * 14 * 128];

// ---------------------------------------------------------------------------
// PTX helpers (base ISA only)
// ---------------------------------------------------------------------------
__device__ __forceinline__ uint32_t smem_u32(const void* p) {
    uint32_t a;
    asm("{ .reg .u64 t; cvta.to.shared.u64 t, %1; cvt.u32.u64 %0, t; }" : "=r"(a) : "l"(p));
    return a;
}
__device__ __forceinline__ void cp16(uint32_t dst, const void* src, bool ok) {
    int sz = ok ? 16 : 0;
    asm volatile("cp.async.cg.shared.global [%0], [%1], 16, %2;"
        :: "r"(dst), "l"(src), "r"(sz) : "memory");
}
__device__ __forceinline__ void ldmatrix_x4(uint32_t* r, uint32_t addr) {
    asm volatile("ldmatrix.sync.aligned.m8n8.x4.shared.b16 {%0,%1,%2,%3}, [%4];"
        : "=r"(r[0]), "=r"(r[1]), "=r"(r[2]), "=r"(r[3]) : "r"(addr));
}
__device__ __forceinline__ void mma16816(float* c, const uint32_t* a, const uint32_t* b) {
    asm volatile("mma.sync.aligned.m16n8k16.row.col.f32.bf16.bf16.f32 "
        "{%0,%1,%2,%3}, {%4,%5,%6,%7}, {%8,%9}, {%0,%1,%2,%3};"
        : "+f"(c[0]), "+f"(c[1]), "+f"(c[2]), "+f"(c[3])
        : "r"(a[0]), "r"(a[1]), "r"(a[2]), "r"(a[3]), "r"(b[0]), "r"(b[1]));
}
__device__ __forceinline__ uint32_t pack_bf16x2(float lo, float hi) {
    uint32_t r;
    asm("cvt.rn.bf16x2.f32 %0, %1, %2;" : "=r"(r) : "f"(hi), "f"(lo));
    return r;
}

// ---------------------------------------------------------------------------
// Block-wide sum reduction (256 threads)
// ---------------------------------------------------------------------------
__device__ __forceinline__ float block_reduce_sum(float v, float* sbuf) {
    int tid = threadIdx.x;
    #pragma unroll
    for (int o = 16; o > 0; o >>= 1) v += __shfl_down_sync(0xffffffffu, v, o);
    if ((tid & 31) == 0) sbuf[tid >> 5] = v;
    __syncthreads();
    float r = 0.f;
    if (tid == 0) {
        #pragma unroll
        for (int i = 0; i < 8; i++) r += sbuf[i];
        sbuf[0] = r;
    }
    __syncthreads();
    r = sbuf[0];
    __syncthreads();
    return r;
}

// ---------------------------------------------------------------------------
// Prep: ternarize weights, fold BN; sign matrices for conv2/3.
// ---------------------------------------------------------------------------
__global__ void prep_kernel(
    const float* __restrict__ w1, const float* __restrict__ g1, const float* __restrict__ b1,
    const float* __restrict__ m1, const float* __restrict__ v1,
    const float* __restrict__ w2, const float* __restrict__ g2, const float* __restrict__ b2,
    const float* __restrict__ m2, const float* __restrict__ v2,
    const float* __restrict__ w3, const float* __restrict__ g3, const float* __restrict__ b3,
    const float* __restrict__ m3, const float* __restrict__ v3,
    const float* __restrict__ wl)
{
    __shared__ float sbuf[8];
    const int t = blockIdx.x;
    const float* w; int n;
    if (t == 0)      { w = w1; n = 864;   }
    else if (t == 1) { w = w2; n = 18432; }
    else if (t == 2) { w = w3; n = 73728; }
    else             { w = wl; n = 1280;  }

    const int tid = threadIdx.x;

    float s = 0.f;
    for (int i = tid; i < n; i += blockDim.x) s += fabsf(w[i]);
    float tot = block_reduce_sum(s, sbuf);
    float delta = 0.7f * tot / (float)n;

    float ms = 0.f, cnt = 0.f;
    for (int i = tid; i < n; i += blockDim.x) {
        float a = fabsf(w[i]);
        if (a > delta) { ms += a; cnt += 1.f; }
    }
    float msum = block_reduce_sum(ms, sbuf);
    float csum = block_reduce_sum(cnt, sbuf);
    float alpha = msum / fmaxf(csum, 1.f);

    if (t == 0) {
        for (int i = tid; i < n; i += blockDim.x) {
            int o = i / 27, rem = i % 27;
            float wv = w[i];
            float q = (fabsf(wv) > delta) ? copysignf(alpha, wv) : 0.f;
            float inv = g1[o] * rsqrtf(v1[o] + BN_EPS);
            g_w1t[rem * 32 + o] = q * inv;
        }
        if (tid < 32) {
            float inv = g1[tid] * rsqrtf(v1[tid] + BN_EPS);
            g_bias1[tid] = b1[tid] - m1[tid] * inv;
        }
    } else if (t == 1) {
        for (int i = tid; i < 64 * 288; i += blockDim.x) {
            int o = i / 288, k = i % 288;
            int tap = k / 32, ic = k % 32;
            float wv = w2[o * 288 + ic * 9 + tap];
            float sv = (fabsf(wv) > delta) ? ((wv > 0.f) ? 1.f : -1.f) : 0.f;
            g_wsgn2[i] = __float2bfloat16(sv);
        }
        if (tid < 64) {
            float inv = g2[tid] * rsqrtf(v2[tid] + BN_EPS);
            g_scale2[tid] = alpha * inv;
            g_bias2[tid]  = b2[tid] - m2[tid] * inv;
        }
    } else if (t == 2) {
        for (int i = tid; i < 128 * 576; i += blockDim.x) {
            int o = i / 576, k = i % 576;
            int tap = k / 64, ic = k % 64;
            float wv = w3[o * 576 + ic * 9 + tap];
            float sv = (fabsf(wv) > delta) ? ((wv > 0.f) ? 1.f : -1.f) : 0.f;
            g_wsgn3[i] = __float2bfloat16(sv);
        }
        if (tid < 128) {
            float inv = g3[tid] * rsqrtf(v3[tid] + BN_EPS);
            g_scale3[tid] = alpha * inv;
            g_bias3[tid]  = b3[tid] - m3[tid] * inv;
        }
    } else {
        for (int i = tid; i < n; i += blockDim.x) {
            float wv = w[i];
            g_wlq[i] = (fabsf(wv) > delta) ? copysignf(alpha, wv) : 0.f;
        }
    }
}

// ---------------------------------------------------------------------------
// conv1: scalar fp32 direct 3x3 s2 (IC=3), NCHW fp32 in -> NHWC bf16 out
// ---------------------------------------------------------------------------
__global__ void conv1_kernel(const float* __restrict__ in, __nv_bfloat16* __restrict__ out,
                             const float* __restrict__ wt, const float* __restrict__ bias)
{
    constexpr int IC = 3, OC = 32, H = 224, W = 224, S = 2, TOH = 8, TOW = 16;
    constexpr int OH = 112, OW = 112;
    constexpr int IH = (TOH - 1) * S + 3;
    constexpr int IW = (TOW - 1) * S + 3;
    constexpr int COLQ = TOW / 4;
    constexpr int NT = 128;

    __shared__ float s_in[IC][IH][IW];
    __shared__ __align__(16) float s_w[IC * 9 * OC];

    const int tid  = threadIdx.x;
    const int ocg  = tid & 3;
    const int pg   = tid >> 2;
    const int row  = pg / COLQ;
    const int colq = pg % COLQ;
    const int n    = blockIdx.z;
    const int ih0  = blockIdx.y * TOH * S - 1;
    const int iw0  = blockIdx.x * TOW * S - 1;

    float acc[4][8];
    #pragma unroll
    for (int p = 0; p < 4; p++)
        #pragma unroll
        for (int j = 0; j < 8; j++) acc[p][j] = 0.f;

    for (int i = tid; i < IC * IH * IW; i += NT) {
        int ic = i / (IH * IW);
        int r  = (i / IW) % IH;
        int c  = i % IW;
        int ih = ih0 + r, iw = iw0 + c;
        float v = 0.f;
        if (ih >= 0 && ih < H && iw >= 0 && iw < W)
            v = in[(((size_t)n * IC + ic) * H + ih) * W + iw];
        s_in[ic][r][c] = v;
    }
    for (int i = tid; i < IC * 9 * OC; i += NT) s_w[i] = wt[i];
    __syncthreads();

    #pragma unroll
    for (int ic = 0; ic < IC; ic++) {
        #pragma unroll
        for (int kh = 0; kh < 3; kh++) {
            #pragma unroll
            for (int kw = 0; kw < 3; kw++) {
                float xv[4];
                #pragma unroll
                for (int p = 0; p < 4; p++)
                    xv[p] = s_in[ic][row * S + kh][(colq * 4 + p) * S + kw];
                const float4* wp =
                    reinterpret_cast<const float4*>(&s_w[(ic * 9 + kh * 3 + kw) * OC + ocg * 8]);
                float4 wa = wp[0], wb = wp[1];
                #pragma unroll
                for (int p = 0; p < 4; p++) {
                    acc[p][0] += xv[p] * wa.x; acc[p][1] += xv[p] * wa.y;
                    acc[p][2] += xv[p] * wa.z; acc[p][3] += xv[p] * wa.w;
                    acc[p][4] += xv[p] * wb.x; acc[p][5] += xv[p] * wb.y;
                    acc[p][6] += xv[p] * wb.z; acc[p][7] += xv[p] * wb.w;
                }
            }
        }
    }

    const int oh = blockIdx.y * TOH + row;
    const int ow = blockIdx.x * TOW + colq * 4;
    float bv[8];
    #pragma unroll
    for (int j = 0; j < 8; j++) bv[j] = bias[ocg * 8 + j];
    #pragma unroll
    for (int p = 0; p < 4; p++) {
        uint32_t pk[4];
        #pragma unroll
        for (int q = 0; q < 4; q++) {
            float lo = fmaxf(acc[p][2 * q]     + bv[2 * q],     0.f);
            float hi = fmaxf(acc[p][2 * q + 1] + bv[2 * q + 1], 0.f);
            pk[q] = pack_bf16x2(lo, hi);
        }
        size_t pix = ((size_t)n * OH + oh) * OW + (ow + p);
        *reinterpret_cast<uint4*>(&out[pix * 32 + ocg * 8]) =
            make_uint4(pk[0], pk[1], pk[2], pk[3]);
    }
}

// ---------------------------------------------------------------------------
// conv2/conv3: persistent implicit GEMM via mma.sync. M=256 px tile, 512 thr
// (16 warps = 4m x 4n). NSTAGE-deep cp.async streaming pipeline with per-tile
// cached im2col decomposition (div/mod once per tile, cheap adds per chunk).
// When NCHUNK==NSTAGE the B sign matrix is stationary: staged only for the
// first tile of each persistent CTA.
// ---------------------------------------------------------------------------
template<int IC, int OC, int H, int W, int S, int TAPS, int NSTAGE>
__global__ void __launch_bounds__(512, 1)
conv_mma(const __nv_bfloat16* __restrict__ in, __nv_bfloat16* __restrict__ out,
         const __nv_bfloat16* __restrict__ wsgn,
         const float* __restrict__ scale, const float* __restrict__ bias)
{
    constexpr int OH = (H - 1) / S + 1, OW = (W - 1) / S + 1;
    constexpr int K  = IC * 9, KC = IC * TAPS, NCHUNK = 9 / TAPS, STEPS = KC / 16;
    constexpr int SAS = KC + 8;
    constexpr int NF  = OC / 32;            // n8-fragments per warp (n-span = OC/4)
    constexpr int AJ  = IC / 8, BJ = KC / 8;
    constexpr int ABYTES = 256 * SAS * 2, BBYTES = OC * SAS * 2;
    constexpr int STAGE  = ABYTES + BBYTES;
    constexpr int NTILE  = (64 * OH * OW) / 256;
    constexpr int UA = (256 * TAPS * AJ) / 512;   // A cp16 per thread per chunk
    constexpr bool BONCE = (NCHUNK == NSTAGE);

    extern __shared__ char smem[];
    const uint32_t sm0 = smem_u32(smem);
    float* s_scale = reinterpret_cast<float*>(smem + NSTAGE * STAGE);
    float* s_bias  = s_scale + OC;

    const int tid  = threadIdx.x, wid = tid >> 5, lane = tid & 31;
    const int m0   = (wid & 3) * 64;
    const int n0   = (wid >> 2) * (OC / 4);
    const int NCTA = gridDim.x;
    const int t0   = blockIdx.x;

    if (tid < OC) { s_scale[tid] = scale[tid]; s_bias[tid] = bias[tid]; }

    // per-tile staging caches (refreshed when the STAGING cursor enters a tile)
    const __nv_bfloat16* cptr[UA];
    int cohs[UA], cows[UA];
    uint32_t a_sdst;
    if constexpr (TAPS == 1) a_sdst = (uint32_t)(((tid / AJ) * SAS + (tid % AJ) * 8) * 2);
    else                     a_sdst = (uint32_t)(((tid / 4) * SAS + (tid % 4) * 8) * 2);

    int s_ts = t0, s_cs = 0;
    auto stage = [&](int buf) {
        if (s_ts < NTILE) {
            if (s_cs == 0) {
                #pragma unroll
                for (int u = 0; u < UA; u++) {
                    int p, tj;
                    if constexpr (TAPS == 1) { p = u * (512 / AJ) + tid / AJ; tj = 0; }
                    else                     { p = (u / 3) * 128 + tid / 4;   tj = u % 3; }
                    int pix = (s_ts << 8) + p;
                    int n = pix / (OH * OW), rem = pix % (OH * OW);
                    int oh = rem / OW, ow = rem % OW;
                    cohs[u] = oh * S - 1;
                    cows[u] = ow * S - 1 + tj;
                    int j = (TAPS == 1) ? (tid % AJ) : (tid % 4);
                    cptr[u] = in + ((size_t)n * H + cohs[u]) * (size_t)W * IC
                                 + (size_t)cows[u] * IC + j * 8;
                }
            }
            int th, tw;
            if constexpr (TAPS == 1) { th = s_cs / 3; tw = s_cs - th * 3; }
            else                     { th = s_cs; tw = 0; }
            const size_t dlt = ((size_t)th * W + tw) * IC;
            const uint32_t ab = sm0 + (uint32_t)(buf * STAGE);
            #pragma unroll
            for (int u = 0; u < UA; u++) {
                int ih = cohs[u] + th, iw = cows[u] + tw;
                bool ok = (unsigned)ih < (unsigned)H && (unsigned)iw < (unsigned)W;
                uint32_t dst;
                if constexpr (TAPS == 1)
                    dst = ab + a_sdst + (uint32_t)(u * (512 / AJ) * SAS * 2);
                else
                    dst = ab + a_sdst + (uint32_t)((u / 3) * 128 * SAS * 2 + (u % 3) * IC * 2);
                cp16(dst, cptr[u] + dlt, ok);
            }
            if (!BONCE || s_ts == t0) {
                const uint32_t bb = ab + ABYTES;
                for (int i = tid; i < OC * BJ; i += 512) {
                    int rr = i / BJ, k0 = (i % BJ) * 8;
                    cp16(bb + (uint32_t)((rr * SAS + k0) * 2),
                         wsgn + (size_t)rr * K + s_cs * KC + k0, true);
                }
            }
        }
        asm volatile("cp.async.commit_group;" ::: "memory");
        if (++s_cs == NCHUNK) { s_cs = 0; s_ts += NCTA; }
    };

    const uint32_t a_off = (uint32_t)(((m0 + (lane & 15)) * SAS + 8 * (lane >> 4)) * 2);
    const uint32_t b_off = (uint32_t)((((lane & 7) + ((lane >> 4) << 3)) * SAS
                                      + 8 * ((lane >> 3) & 1)) * 2);

    #pragma unroll
    for (int i = 0; i < NSTAGE - 1; i++) stage(i);

    int buf = 0;
    for (int t = t0; t < NTILE; t += NCTA) {
        float acc[4][NF][4];
        #pragma unroll
        for (int fm = 0; fm < 4; fm++)
            #pragma unroll
            for (int fn = 0; fn < NF; fn++)
                #pragma unroll
                for (int q = 0; q < 4; q++) acc[fm][fn][q] = 0.f;

        for (int c = 0; c < NCHUNK; c++) {
            asm volatile("cp.async.wait_group 1;" ::: "memory");
            __syncthreads();
            stage((buf + NSTAGE - 1) % NSTAGE);

            const uint32_t abase = sm0 + (uint32_t)(buf * STAGE) + a_off;
            const uint32_t bbase = sm0 + (uint32_t)(buf * STAGE + ABYTES) + b_off;
            #pragma unroll
            for (int s = 0; s < STEPS; s++) {
                uint32_t a[4][4];
                #pragma unroll
                for (int fm = 0; fm < 4; fm++)
                    ldmatrix_x4(a[fm], abase + (uint32_t)(s * 32 + fm * 16 * SAS * 2));
                uint32_t b[NF][2];
                #pragma unroll
                for (int f2 = 0; f2 < NF / 2; f2++) {
                    uint32_t r[4];
                    ldmatrix_x4(r, bbase + (uint32_t)((n0 + f2 * 16) * SAS * 2 + s * 32));
                    b[2 * f2][0] = r[0]; b[2 * f2][1] = r[1];
                    b[2 * f2 + 1][0] = r[2]; b[2 * f2 + 1][1] = r[3];
                }
                #pragma unroll
                for (int fm = 0; fm < 4; fm++)
                    #pragma unroll
                    for (int fn = 0; fn < NF; fn++)
                        mma16816(acc[fm][fn], a[fm], b[fn]);
            }
            buf = (buf + 1) % NSTAGE;
        }

        // ---- epilogue: scale+bias+relu -> bf16 pairs, NHWC store
        const int pix0 = t << 8;
        #pragma unroll
        for (int fm = 0; fm < 4; fm++) {
            const int r0 = pix0 + m0 + fm * 16 + (lane >> 2);
            #pragma unroll
            for (int fn = 0; fn < NF; fn++) {
                const int oc = n0 + fn * 8 + 2 * (lane & 3);
                const float sc0 = s_scale[oc], sc1 = s_scale[oc + 1];
                const float bb0 = s_bias[oc],  bb1 = s_bias[oc + 1];
                const float* cc = acc[fm][fn];
                uint32_t p0 = pack_bf16x2(fmaxf(cc[0] * sc0 + bb0, 0.f),
                                          fmaxf(cc[1] * sc1 + bb1, 0.f));
                uint32_t p1 = pack_bf16x2(fmaxf(cc[2] * sc0 + bb0, 0.f),
                                          fmaxf(cc[3] * sc1 + bb1, 0.f));
                *reinterpret_cast<uint32_t*>(out + (size_t)r0 * OC + oc)       = p0;
                *reinterpret_cast<uint32_t*>(out + (size_t)(r0 + 8) * OC + oc) = p1;
            }
        }
    }
}

// ---------------------------------------------------------------------------
// Global average pool, 2-stage deterministic. NHWC bf16 [64][3136][128].
// ---------------------------------------------------------------------------
__global__ void pool_stage1(const __nv_bfloat16* __restrict__ h3)
{
    const int n = blockIdx.x, sl = blockIdx.y, c = threadIdx.x;
    const __nv_bfloat16* p = h3 + ((size_t)n * 3136 + sl * 224) * 128 + c;
    float s = 0.f;
    #pragma unroll 8
    for (int i = 0; i < 224; i++) s += __bfloat162float(p[(size_t)i * 128]);
    g_poolpart[(n * 14 + sl) * 128 + c] = s;
}
__global__ void pool_stage2()
{
    const int n = blockIdx.x, c = threadIdx.x;
    float s = 0.f;
    #pragma unroll
    for (int i = 0; i < 14; i++) s += g_poolpart[(n * 14 + i) * 128 + c];
    g_pool[n * 128 + c] = s * (1.f / 3136.f);
}

// ---------------------------------------------------------------------------
// Linear: out[n,j] = pool[n,:] . wlq[j,:] + bl[j]   (64x10)
// ---------------------------------------------------------------------------
__global__ void linear_kernel(const float* __restrict__ bl, float* __restrict__ out)
{
    int tid = blockIdx.x * blockDim.x + threadIdx.x;
    if (tid >= 640) return;
    int n = tid / 10, j = tid % 10;
    const float* hp = &g_pool[n * 128];
    const float* wp = &g_wlq[j * 128];
    float s = bl[j];
    #pragma unroll 8
    for (int c = 0; c < 128; c++) s += hp[c] * wp[c];
    out[tid] = s;
}

// ---------------------------------------------------------------------------
// Launch
// ---------------------------------------------------------------------------
extern "C" void kernel_launch(void* const* d_in, const int* in_sizes, int n_in,
                              void* d_out, int out_size)
{
    const float* x  = (const float*)d_in[0];
    const float* w1 = (const float*)d_in[1];
    const float* g1 = (const float*)d_in[2];
    const float* b1 = (const float*)d_in[3];
    const float* m1 = (const float*)d_in[4];
    const float* v1 = (const float*)d_in[5];
    const float* w2 = (const float*)d_in[6];
    const float* g2 = (const float*)d_in[7];
    const float* b2 = (const float*)d_in[8];
    const float* m2 = (const float*)d_in[9];
    const float* v2 = (const float*)d_in[10];
    const float* w3 = (const float*)d_in[11];
    const float* g3 = (const float*)d_in[12];
    const float* b3 = (const float*)d_in[13];
    const float* m3 = (const float*)d_in[14];
    const float* v3 = (const float*)d_in[15];
    const float* wl = (const float*)d_in[16];
    const float* bl = (const float*)d_in[17];

    __nv_bfloat16 *h1, *h2, *h3, *ws2, *ws3;
    float *w1t, *bb1, *sc2, *bb2, *sc3, *bb3;
    cudaGetSymbolAddress((void**)&h1,  g_h1);
    cudaGetSymbolAddress((void**)&h2,  g_h2);
    cudaGetSymbolAddress((void**)&h3,  g_h3);
    cudaGetSymbolAddress((void**)&ws2, g_wsgn2);
    cudaGetSymbolAddress((void**)&ws3, g_wsgn3);
    cudaGetSymbolAddress((void**)&w1t, g_w1t);
    cudaGetSymbolAddress((void**)&bb1, g_bias1);
    cudaGetSymbolAddress((void**)&sc2, g_scale2);
    cudaGetSymbolAddress((void**)&bb2, g_bias2);
    cudaGetSymbolAddress((void**)&sc3, g_scale3);
    cudaGetSymbolAddress((void**)&bb3, g_bias3);

    // dynamic smem: NSTAGE*(A 256xSAS + B OCxSAS) + scale/bias
    const int SM2 = 3 * (256 * 104 * 2 + 64 * 104 * 2) + 2 * 64 * 4;     // 200192
    const int SM3 = 3 * (256 * 72 * 2 + 128 * 72 * 2) + 2 * 128 * 4;     // 166912
    cudaFuncSetAttribute(conv_mma<32, 64, 112, 112, 1, 3, 3>,
                         cudaFuncAttributeMaxDynamicSharedMemorySize, SM2);
    cudaFuncSetAttribute(conv_mma<64, 128, 112, 112, 2, 1, 3>,
                         cudaFuncAttributeMaxDynamicSharedMemorySize, SM3);

    // 1. ternarize + fold
    prep_kernel<<<4, 256>>>(w1, g1, b1, m1, v1,
                            w2, g2, b2, m2, v2,
                            w3, g3, b3, m3, v3, wl);

    // 2. conv1: 3->32, s2, NCHW fp32 -> NHWC bf16
    conv1_kernel<<<dim3(7, 14, 64), 128>>>(x, h1, w1t, bb1);

    // 3. conv2: 32->64, s1 (M=256 streaming pipeline, B stationary)
    conv_mma<32, 64, 112, 112, 1, 3, 3><<<152, 512, SM2>>>(h1, h2, ws2, sc2, bb2);

    // 4. conv3: 64->128, s2 (M=256 streaming pipeline)
    conv_mma<64, 128, 112, 112, 2, 1, 3><<<152, 512, SM3>>>(h2, h3, ws3, sc3, bb3);

    // 5. global average pool (2-stage, deterministic)
    pool_stage1<<<dim3(64, 14), 128>>>(h3);
    pool_stage2<<<64, 128>>>();

    // 6. linear head
    linear_kernel<<<3, 256>>>(bl, (float*)d_out);
}

// round 12
// speedup vs baseline: 1.5622x; 1.5622x over previous
#include <cuda_runtime.h>
#include <cuda_bf16.h>
#include <stdint.h>

#define BN_EPS 1e-5f

// ---------------------------------------------------------------------------
// Device-global scratch (no allocations allowed)
// ---------------------------------------------------------------------------
__device__ __nv_bfloat16 g_h1[(size_t)64 * 112 * 112 * 32];   // conv1 out, NHWC bf16
__device__ __nv_bfloat16 g_h2[(size_t)64 * 112 * 112 * 64];   // conv2 out, NHWC bf16
__device__ __nv_bfloat16 g_h3[(size_t)64 * 56 * 56 * 128];    // conv3 out, NHWC bf16
__device__ float         g_w1t[27 * 32];                      // conv1 folded fp32 [k][oc]
__device__ __nv_bfloat16 g_wsgn2[64 * 288];                   // conv2 signs [oc][k], k=tap*32+ic
__device__ __nv_bfloat16 g_wsgn3[128 * 576];                  // conv3 signs [oc][k], k=tap*64+ic
__device__ float g_bias1[32];
__device__ float g_scale2[64],  g_bias2[64];
__device__ float g_scale3[128], g_bias3[128];
__device__ float g_wlq[10 * 128];
__device__ float g_pool[64 * 128];
__device__ float g_poolpart[64 * 28 * 128];

// ---------------------------------------------------------------------------
// PTX helpers (base ISA only)
// ---------------------------------------------------------------------------
__device__ __forceinline__ uint32_t smem_u32(const void* p) {
    uint32_t a;
    asm("{ .reg .u64 t; cvta.to.shared.u64 t, %1; cvt.u32.u64 %0, t; }" : "=r"(a) : "l"(p));
    return a;
}
__device__ __forceinline__ void cp16(uint32_t dst, const void* src, bool ok) {
    int sz = ok ? 16 : 0;
    asm volatile("cp.async.cg.shared.global [%0], [%1], 16, %2;"
        :: "r"(dst), "l"(src), "r"(sz) : "memory");
}
__device__ __forceinline__ void ldmatrix_x4(uint32_t* r, uint32_t addr) {
    asm volatile("ldmatrix.sync.aligned.m8n8.x4.shared.b16 {%0,%1,%2,%3}, [%4];"
        : "=r"(r[0]), "=r"(r[1]), "=r"(r[2]), "=r"(r[3]) : "r"(addr));
}
__device__ __forceinline__ void mma16816(float* c, const uint32_t* a, const uint32_t* b) {
    asm volatile("mma.sync.aligned.m16n8k16.row.col.f32.bf16.bf16.f32 "
        "{%0,%1,%2,%3}, {%4,%5,%6,%7}, {%8,%9}, {%0,%1,%2,%3};"
        : "+f"(c[0]), "+f"(c[1]), "+f"(c[2]), "+f"(c[3])
        : "r"(a[0]), "r"(a[1]), "r"(a[2]), "r"(a[3]), "r"(b[0]), "r"(b[1]));
}
__device__ __forceinline__ uint32_t pack_bf16x2(float lo, float hi) {
    uint32_t r;
    asm("cvt.rn.bf16x2.f32 %0, %1, %2;" : "=r"(r) : "f"(hi), "f"(lo));
    return r;
}

// ---------------------------------------------------------------------------
// Block-wide sum reduction (256 threads)
// ---------------------------------------------------------------------------
__device__ __forceinline__ float block_reduce_sum(float v, float* sbuf) {
    int tid = threadIdx.x;
    #pragma unroll
    for (int o = 16; o > 0; o >>= 1) v += __shfl_down_sync(0xffffffffu, v, o);
    if ((tid & 31) == 0) sbuf[tid >> 5] = v;
    __syncthreads();
    float r = 0.f;
    if (tid == 0) {
        #pragma unroll
        for (int i = 0; i < 8; i++) r += sbuf[i];
        sbuf[0] = r;
    }
    __syncthreads();
    r = sbuf[0];
    __syncthreads();
    return r;
}

// ---------------------------------------------------------------------------
// Prep: ternarize weights, fold BN; sign matrices for conv2/3.
// ---------------------------------------------------------------------------
__global__ void prep_kernel(
    const float* __restrict__ w1, const float* __restrict__ g1, const float* __restrict__ b1,
    const float* __restrict__ m1, const float* __restrict__ v1,
    const float* __restrict__ w2, const float* __restrict__ g2, const float* __restrict__ b2,
    const float* __restrict__ m2, const float* __restrict__ v2,
    const float* __restrict__ w3, const float* __restrict__ g3, const float* __restrict__ b3,
    const float* __restrict__ m3, const float* __restrict__ v3,
    const float* __restrict__ wl)
{
    __shared__ float sbuf[8];
    const int t = blockIdx.x;
    const float* w; int n;
    if (t == 0)      { w = w1; n = 864;   }
    else if (t == 1) { w = w2; n = 18432; }
    else if (t == 2) { w = w3; n = 73728; }
    else             { w = wl; n = 1280;  }

    const int tid = threadIdx.x;

    float s = 0.f;
    for (int i = tid; i < n; i += blockDim.x) s += fabsf(w[i]);
    float tot = block_reduce_sum(s, sbuf);
    float delta = 0.7f * tot / (float)n;

    float ms = 0.f, cnt = 0.f;
    for (int i = tid; i < n; i += blockDim.x) {
        float a = fabsf(w[i]);
        if (a > delta) { ms += a; cnt += 1.f; }
    }
    float msum = block_reduce_sum(ms, sbuf);
    float csum = block_reduce_sum(cnt, sbuf);
    float alpha = msum / fmaxf(csum, 1.f);

    if (t == 0) {
        for (int i = tid; i < n; i += blockDim.x) {
            int o = i / 27, rem = i % 27;
            float wv = w[i];
            float q = (fabsf(wv) > delta) ? copysignf(alpha, wv) : 0.f;
            float inv = g1[o] * rsqrtf(v1[o] + BN_EPS);
            g_w1t[rem * 32 + o] = q * inv;
        }
        if (tid < 32) {
            float inv = g1[tid] * rsqrtf(v1[tid] + BN_EPS);
            g_bias1[tid] = b1[tid] - m1[tid] * inv;
        }
    } else if (t == 1) {
        for (int i = tid; i < 64 * 288; i += blockDim.x) {
            int o = i / 288, k = i % 288;
            int tap = k / 32, ic = k % 32;
            float wv = w2[o * 288 + ic * 9 + tap];
            float sv = (fabsf(wv) > delta) ? ((wv > 0.f) ? 1.f : -1.f) : 0.f;
            g_wsgn2[i] = __float2bfloat16(sv);
        }
        if (tid < 64) {
            float inv = g2[tid] * rsqrtf(v2[tid] + BN_EPS);
            g_scale2[tid] = alpha * inv;
            g_bias2[tid]  = b2[tid] - m2[tid] * inv;
        }
    } else if (t == 2) {
        for (int i = tid; i < 128 * 576; i += blockDim.x) {
            int o = i / 576, k = i % 576;
            int tap = k / 64, ic = k % 64;
            float wv = w3[o * 576 + ic * 9 + tap];
            float sv = (fabsf(wv) > delta) ? ((wv > 0.f) ? 1.f : -1.f) : 0.f;
            g_wsgn3[i] = __float2bfloat16(sv);
        }
        if (tid < 128) {
            float inv = g3[tid] * rsqrtf(v3[tid] + BN_EPS);
            g_scale3[tid] = alpha * inv;
            g_bias3[tid]  = b3[tid] - m3[tid] * inv;
        }
    } else {
        for (int i = tid; i < n; i += blockDim.x) {
            float wv = w[i];
            g_wlq[i] = (fabsf(wv) > delta) ? copysignf(alpha, wv) : 0.f;
        }
    }
}

// ---------------------------------------------------------------------------
// conv1: scalar fp32 direct 3x3 s2 (IC=3), NCHW fp32 in -> NHWC bf16 out
// ---------------------------------------------------------------------------
__global__ void conv1_kernel(const float* __restrict__ in, __nv_bfloat16* __restrict__ out,
                             const float* __restrict__ wt, const float* __restrict__ bias)
{
    constexpr int IC = 3, OC = 32, H = 224, W = 224, S = 2, TOH = 8, TOW = 16;
    constexpr int OH = 112, OW = 112;
    constexpr int IH = (TOH - 1) * S + 3;
    constexpr int IW = (TOW - 1) * S + 3;
    constexpr int COLQ = TOW / 4;
    constexpr int NT = 128;

    __shared__ float s_in[IC][IH][IW];
    __shared__ __align__(16) float s_w[IC * 9 * OC];

    const int tid  = threadIdx.x;
    const int ocg  = tid & 3;
    const int pg   = tid >> 2;
    const int row  = pg / COLQ;
    const int colq = pg % COLQ;
    const int n    = blockIdx.z;
    const int ih0  = blockIdx.y * TOH * S - 1;
    const int iw0  = blockIdx.x * TOW * S - 1;

    float acc[4][8];
    #pragma unroll
    for (int p = 0; p < 4; p++)
        #pragma unroll
        for (int j = 0; j < 8; j++) acc[p][j] = 0.f;

    for (int i = tid; i < IC * IH * IW; i += NT) {
        int ic = i / (IH * IW);
        int r  = (i / IW) % IH;
        int c  = i % IW;
        int ih = ih0 + r, iw = iw0 + c;
        float v = 0.f;
        if (ih >= 0 && ih < H && iw >= 0 && iw < W)
            v = in[(((size_t)n * IC + ic) * H + ih) * W + iw];
        s_in[ic][r][c] = v;
    }
    for (int i = tid; i < IC * 9 * OC; i += NT) s_w[i] = wt[i];
    __syncthreads();

    #pragma unroll
    for (int ic = 0; ic < IC; ic++) {
        #pragma unroll
        for (int kh = 0; kh < 3; kh++) {
            #pragma unroll
            for (int kw = 0; kw < 3; kw++) {
                float xv[4];
                #pragma unroll
                for (int p = 0; p < 4; p++)
                    xv[p] = s_in[ic][row * S + kh][(colq * 4 + p) * S + kw];
                const float4* wp =
                    reinterpret_cast<const float4*>(&s_w[(ic * 9 + kh * 3 + kw) * OC + ocg * 8]);
                float4 wa = wp[0], wb = wp[1];
                #pragma unroll
                for (int p = 0; p < 4; p++) {
                    acc[p][0] += xv[p] * wa.x; acc[p][1] += xv[p] * wa.y;
                    acc[p][2] += xv[p] * wa.z; acc[p][3] += xv[p] * wa.w;
                    acc[p][4] += xv[p] * wb.x; acc[p][5] += xv[p] * wb.y;
                    acc[p][6] += xv[p] * wb.z; acc[p][7] += xv[p] * wb.w;
                }
            }
        }
    }

    const int oh = blockIdx.y * TOH + row;
    const int ow = blockIdx.x * TOW + colq * 4;
    float bv[8];
    #pragma unroll
    for (int j = 0; j < 8; j++) bv[j] = bias[ocg * 8 + j];
    #pragma unroll
    for (int p = 0; p < 4; p++) {
        uint32_t pk[4];
        #pragma unroll
        for (int q = 0; q < 4; q++) {
            float lo = fmaxf(acc[p][2 * q]     + bv[2 * q],     0.f);
            float hi = fmaxf(acc[p][2 * q + 1] + bv[2 * q + 1], 0.f);
            pk[q] = pack_bf16x2(lo, hi);
        }
        size_t pix = ((size_t)n * OH + oh) * OW + (ow + p);
        *reinterpret_cast<uint4*>(&out[pix * 32 + ocg * 8]) =
            make_uint4(pk[0], pk[1], pk[2], pk[3]);
    }
}

// ---------------------------------------------------------------------------
// conv2/conv3: implicit GEMM via mma.sync, one tile (128 px x OC) per CTA,
// cp.async pipeline with ONE __syncthreads per chunk.
//  NSTAGE==2 (conv2): wait(c) -> sync -> stage(c+1) -> MMA(c)
//     (sync proves MMA(c-1) done everywhere, so buffer (c+1)&1 is free;
//      chunk c+1 latency hides behind MMA(c))
//  NSTAGE==3 (conv3): wait(c) -> sync -> MMA(c) -> stage(c+2)
//     (buffer (c+2)%3 was consumed at MMA(c-1), covered by the same sync;
//      chunk c+1 was staged a full chunk earlier)
// ---------------------------------------------------------------------------
template<int IC, int OC, int H, int W, int S, int TAPS, int NSTAGE>
__global__ void __launch_bounds__(256, 2)
conv_mma(const __nv_bfloat16* __restrict__ in, __nv_bfloat16* __restrict__ out,
         const __nv_bfloat16* __restrict__ wsgn,
         const float* __restrict__ scale, const float* __restrict__ bias)
{
    constexpr int OH = (H - 1) / S + 1, OW = (W - 1) / S + 1;
    constexpr int K  = IC * 9, KC = IC * TAPS, NCHUNK = 9 / TAPS, STEPS = KC / 16;
    constexpr int SAS = KC + 8;            // row stride: 208B/144B -> conflict-free LDSM
    constexpr int NF  = OC / 16;           // n8-fragments per warp (warp n-span = OC/2)
    constexpr int AJ  = IC / 8, BJ = KC / 8;
    constexpr int ABYTES = 128 * SAS * 2, BBYTES = OC * SAS * 2;
    constexpr int STAGE  = ABYTES + BBYTES;

    extern __shared__ char smem[];
    const uint32_t sm0 = smem_u32(smem);
    float* s_scale = reinterpret_cast<float*>(smem + NSTAGE * STAGE);
    float* s_bias  = s_scale + OC;

    const int tid  = threadIdx.x, wid = tid >> 5, lane = tid & 31;
    const int pix0 = blockIdx.x << 7;
    const int m0   = (wid & 3) * 32;
    const int n0   = (wid >> 2) * (OC / 2);

    if (tid < OC) { s_scale[tid] = scale[tid]; s_bias[tid] = bias[tid]; }

    auto stage = [&](int chunk) {
        if (chunk < NCHUNK) {
            const int buf = chunk % NSTAGE, t0 = chunk * TAPS;
            const uint32_t ab = sm0 + (uint32_t)(buf * STAGE);
            #pragma unroll
            for (int i = tid; i < 128 * TAPS * AJ; i += 256) {
                int p    = i / (TAPS * AJ);
                int r    = i % (TAPS * AJ);
                int tapl = r / AJ, j = r % AJ;
                int tap  = t0 + tapl;
                int pix  = pix0 + p;
                int n    = pix / (OH * OW), rem = pix % (OH * OW);
                int oh   = rem / OW, ow = rem % OW;
                int ih   = oh * S + tap / 3 - 1;
                int iw   = ow * S + tap % 3 - 1;
                bool ok  = (unsigned)ih < (unsigned)H && (unsigned)iw < (unsigned)W;
                cp16(ab + (uint32_t)((p * SAS + tapl * IC + j * 8) * 2),
                     in + ((size_t)(n * H + ih) * W + iw) * IC + j * 8, ok);
            }
            const uint32_t bb = ab + ABYTES;
            #pragma unroll
            for (int i = tid; i < OC * BJ; i += 256) {
                int rr = i / BJ, k0 = (i % BJ) * 8;
                cp16(bb + (uint32_t)((rr * SAS + k0) * 2),
                     wsgn + (size_t)rr * K + t0 * IC + k0, true);
            }
        }
        asm volatile("cp.async.commit_group;" ::: "memory");
    };

    const uint32_t a_off = (uint32_t)(((m0 + (lane & 15)) * SAS + 8 * (lane >> 4)) * 2);
    const uint32_t b_off = (uint32_t)((((lane & 7) + ((lane >> 4) << 3)) * SAS
                                      + 8 * ((lane >> 3) & 1)) * 2);

    float acc[2][NF][4];
    #pragma unroll
    for (int fm = 0; fm < 2; fm++)
        #pragma unroll
        for (int fn = 0; fn < NF; fn++)
            #pragma unroll
            for (int q = 0; q < 4; q++) acc[fm][fn][q] = 0.f;

    // prologue
    stage(0);
    if constexpr (NSTAGE == 3) stage(1);

    for (int c = 0; c < NCHUNK; c++) {
        if constexpr (NSTAGE == 2) {
            // pending = {c}: wait it, sync, then stage c+1 (hidden behind MMA c)
            asm volatile("cp.async.wait_group 0;" ::: "memory");
            __syncthreads();
            stage(c + 1);
        } else {
            // pending = {c, c+1}: all but newest complete -> c ready
            asm volatile("cp.async.wait_group 1;" ::: "memory");
            __syncthreads();
        }

        const int buf = c % NSTAGE;
        const uint32_t abase = sm0 + (uint32_t)(buf * STAGE) + a_off;
        const uint32_t bbase = sm0 + (uint32_t)(buf * STAGE + ABYTES) + b_off;
        #pragma unroll
        for (int s = 0; s < STEPS; s++) {
            uint32_t a[2][4];
            ldmatrix_x4(a[0], abase + (uint32_t)(s * 32));
            ldmatrix_x4(a[1], abase + (uint32_t)(s * 32 + 16 * SAS * 2));
            uint32_t b[NF][2];
            #pragma unroll
            for (int f2 = 0; f2 < NF / 2; f2++) {
                uint32_t r[4];
                ldmatrix_x4(r, bbase + (uint32_t)((n0 + f2 * 16) * SAS * 2 + s * 32));
                b[2 * f2][0] = r[0]; b[2 * f2][1] = r[1];
                b[2 * f2 + 1][0] = r[2]; b[2 * f2 + 1][1] = r[3];
            }
            #pragma unroll
            for (int fm = 0; fm < 2; fm++)
                #pragma unroll
                for (int fn = 0; fn < NF; fn++)
                    mma16816(acc[fm][fn], a[fm], b[fn]);
        }

        if constexpr (NSTAGE == 3) stage(c + 2);
    }

    // ---- epilogue: scale+bias+relu -> bf16 pairs, NHWC store
    #pragma unroll
    for (int fm = 0; fm < 2; fm++) {
        const int r0 = pix0 + m0 + fm * 16 + (lane >> 2);
        #pragma unroll
        for (int fn = 0; fn < NF; fn++) {
            const int oc = n0 + fn * 8 + 2 * (lane & 3);
            const float sc0 = s_scale[oc], sc1 = s_scale[oc + 1];
            const float bb0 = s_bias[oc],  bb1 = s_bias[oc + 1];
            const float* cc = acc[fm][fn];
            uint32_t p0 = pack_bf16x2(fmaxf(cc[0] * sc0 + bb0, 0.f),
                                      fmaxf(cc[1] * sc1 + bb1, 0.f));
            uint32_t p1 = pack_bf16x2(fmaxf(cc[2] * sc0 + bb0, 0.f),
                                      fmaxf(cc[3] * sc1 + bb1, 0.f));
            *reinterpret_cast<uint32_t*>(out + (size_t)r0 * OC + oc)       = p0;
            *reinterpret_cast<uint32_t*>(out + (size_t)(r0 + 8) * OC + oc) = p1;
        }
    }
}

// ---------------------------------------------------------------------------
// Global average pool, 2-stage deterministic, vectorized (8 ch per thread).
// h3: NHWC bf16 [64][3136][128].
// ---------------------------------------------------------------------------
__global__ void pool_stage1(const __nv_bfloat16* __restrict__ h3)
{
    const int n = blockIdx.x, sl = blockIdx.y;
    const int pl = threadIdx.x & 7, cg = threadIdx.x >> 3;   // 16 cg x 8 px-lanes
    const __nv_bfloat16* base = h3 + ((size_t)n * 3136 + sl * 112) * 128 + cg * 8;
    float s[8];
    #pragma unroll
    for (int j = 0; j < 8; j++) s[j] = 0.f;
    #pragma unroll 2
    for (int it = 0; it < 14; it++) {
        uint4 v = *reinterpret_cast<const uint4*>(base + (size_t)(it * 8 + pl) * 128);
        const __nv_bfloat16* pv = reinterpret_cast<const __nv_bfloat16*>(&v);
        #pragma unroll
        for (int j = 0; j < 8; j++) s[j] += __bfloat162float(pv[j]);
    }
    #pragma unroll
    for (int o = 4; o > 0; o >>= 1)
        #pragma unroll
        for (int j = 0; j < 8; j++) s[j] += __shfl_down_sync(0xffffffffu, s[j], o);
    if (pl == 0) {
        #pragma unroll
        for (int j = 0; j < 8; j++)
            g_poolpart[((size_t)n * 28 + sl) * 128 + cg * 8 + j] = s[j];
    }
}
__global__ void pool_stage2()
{
    const int n = blockIdx.x, c = threadIdx.x;
    float s = 0.f;
    #pragma unroll
    for (int i = 0; i < 28; i++) s += g_poolpart[((size_t)n * 28 + i) * 128 + c];
    g_pool[n * 128 + c] = s * (1.f / 3136.f);
}

// ---------------------------------------------------------------------------
// Linear: out[n,j] = pool[n,:] . wlq[j,:] + bl[j]   (64x10)
// ---------------------------------------------------------------------------
__global__ void linear_kernel(const float* __restrict__ bl, float* __restrict__ out)
{
    int tid = blockIdx.x * blockDim.x + threadIdx.x;
    if (tid >= 640) return;
    int n = tid / 10, j = tid % 10;
    const float* hp = &g_pool[n * 128];
    const float* wp = &g_wlq[j * 128];
    float s = bl[j];
    #pragma unroll 8
    for (int c = 0; c < 128; c++) s += hp[c] * wp[c];
    out[tid] = s;
}

// ---------------------------------------------------------------------------
// Launch
// ---------------------------------------------------------------------------
extern "C" void kernel_launch(void* const* d_in, const int* in_sizes, int n_in,
                              void* d_out, int out_size)
{
    const float* x  = (const float*)d_in[0];
    const float* w1 = (const float*)d_in[1];
    const float* g1 = (const float*)d_in[2];
    const float* b1 = (const float*)d_in[3];
    const float* m1 = (const float*)d_in[4];
    const float* v1 = (const float*)d_in[5];
    const float* w2 = (const float*)d_in[6];
    const float* g2 = (const float*)d_in[7];
    const float* b2 = (const float*)d_in[8];
    const float* m2 = (const float*)d_in[9];
    const float* v2 = (const float*)d_in[10];
    const float* w3 = (const float*)d_in[11];
    const float* g3 = (const float*)d_in[12];
    const float* b3 = (const float*)d_in[13];
    const float* m3 = (const float*)d_in[14];
    const float* v3 = (const float*)d_in[15];
    const float* wl = (const float*)d_in[16];
    const float* bl = (const float*)d_in[17];

    __nv_bfloat16 *h1, *h2, *h3, *ws2, *ws3;
    float *w1t, *bb1, *sc2, *bb2, *sc3, *bb3;
    cudaGetSymbolAddress((void**)&h1,  g_h1);
    cudaGetSymbolAddress((void**)&h2,  g_h2);
    cudaGetSymbolAddress((void**)&h3,  g_h3);
    cudaGetSymbolAddress((void**)&ws2, g_wsgn2);
    cudaGetSymbolAddress((void**)&ws3, g_wsgn3);
    cudaGetSymbolAddress((void**)&w1t, g_w1t);
    cudaGetSymbolAddress((void**)&bb1, g_bias1);
    cudaGetSymbolAddress((void**)&sc2, g_scale2);
    cudaGetSymbolAddress((void**)&bb2, g_bias2);
    cudaGetSymbolAddress((void**)&sc3, g_scale3);
    cudaGetSymbolAddress((void**)&bb3, g_bias3);

    // dynamic smem: NSTAGE*(A + B) + scale/bias
    const int SM2 = 2 * (128 * 104 * 2 + 64 * 104 * 2) + 2 * 64 * 4;    // 80384
    const int SM3 = 3 * (128 * 72 * 2 + 128 * 72 * 2) + 2 * 128 * 4;    // 111616
    cudaFuncSetAttribute(conv_mma<32, 64, 112, 112, 1, 3, 2>,
                         cudaFuncAttributeMaxDynamicSharedMemorySize, SM2);
    cudaFuncSetAttribute(conv_mma<64, 128, 112, 112, 2, 1, 3>,
                         cudaFuncAttributeMaxDynamicSharedMemorySize, SM3);

    // 1. ternarize + fold
    prep_kernel<<<4, 256>>>(w1, g1, b1, m1, v1,
                            w2, g2, b2, m2, v2,
                            w3, g3, b3, m3, v3, wl);

    // 2. conv1: 3->32, s2, NCHW fp32 -> NHWC bf16
    conv1_kernel<<<dim3(7, 14, 64), 128>>>(x, h1, w1t, bb1);

    // 3. conv2: 32->64, s1 (1-sync/chunk, depth-2, stage hidden behind MMA)
    conv_mma<32, 64, 112, 112, 1, 3, 2><<<6272, 256, SM2>>>(h1, h2, ws2, sc2, bb2);

    // 4. conv3: 64->128, s2 (1-sync/chunk, depth-3 streaming)
    conv_mma<64, 128, 112, 112, 2, 1, 3><<<1568, 256, SM3>>>(h2, h3, ws3, sc3, bb3);

    // 5. global average pool (2-stage, vectorized, deterministic)
    pool_stage1<<<dim3(64, 28), 128>>>(h3);
    pool_stage2<<<64, 128>>>();

    // 6. linear head
    linear_kernel<<<3, 256>>>(bl, (float*)d_out);
}